// round 1
// baseline (speedup 1.0000x reference)
#include <cuda_runtime.h>
#include <math.h>

#define NB 4
#define SEQL 2048
#define DMODEL 512
#define NHEAD 8
#define HDIM 64
#define WINDOW 256
#define MTOT (NB*SEQL)   // 8192

// Scratch (device globals; no allocation allowed)
__device__ float g_Q[NB*NHEAD*SEQL*HDIM];    // [B,H,L,d]
__device__ float g_K[NB*NHEAD*SEQL*HDIM];
__device__ float g_V[NB*NHEAD*SEQL*HDIM];
__device__ float g_ctx[MTOT*DMODEL];         // [B*L, H*dv]
__device__ float g_pre[MTOT*DMODEL];         // pre-LayerNorm

// ---------------------------------------------------------------------------
// SGEMM: C = A[M,512] @ W[512,512].  Block tile 128x128, BK=16, 256 threads,
// 8x8 register micro-tile per thread.
// MODE 0: store permuted to [B,H,L,d] (QKV projection)
// MODE 1: store C + resid to out (row-major [M,512])
// ---------------------------------------------------------------------------
template<int MODE>
__global__ __launch_bounds__(256)
void gemm512_kernel(const float* __restrict__ A, const float* __restrict__ W,
                    const float* __restrict__ resid, float* __restrict__ out)
{
    __shared__ float sA[16][132];   // A tile transposed: sA[k][m]
    __shared__ float sB[16][132];   // W tile: sB[k][n]

    const int tid = threadIdx.x;
    const int tx  = tid & 15;
    const int ty  = tid >> 4;
    const int bx  = blockIdx.x;   // N tile
    const int by  = blockIdx.y;   // M tile

    const float* Ab = A + (size_t)by * 128 * DMODEL;
    const float* Wb = W + bx * 128;

    float acc[8][8];
    #pragma unroll
    for (int i = 0; i < 8; i++)
        #pragma unroll
        for (int j = 0; j < 8; j++) acc[i][j] = 0.0f;

    for (int k0 = 0; k0 < DMODEL; k0 += 16) {
        // A tile: 128 rows x 16 cols = 512 float4, 2 per thread, store transposed
        #pragma unroll
        for (int r = 0; r < 2; r++) {
            int f   = tid + r * 256;
            int row = f >> 2;
            int c4  = (f & 3) << 2;
            float4 v = *(const float4*)(Ab + (size_t)row * DMODEL + k0 + c4);
            sA[c4 + 0][row] = v.x;
            sA[c4 + 1][row] = v.y;
            sA[c4 + 2][row] = v.z;
            sA[c4 + 3][row] = v.w;
        }
        // W tile: 16 rows x 128 cols = 512 float4, direct
        #pragma unroll
        for (int r = 0; r < 2; r++) {
            int f   = tid + r * 256;
            int row = f >> 5;
            int c4  = (f & 31) << 2;
            *(float4*)&sB[row][c4] =
                *(const float4*)(Wb + (size_t)(k0 + row) * DMODEL + c4);
        }
        __syncthreads();

        #pragma unroll
        for (int kk = 0; kk < 16; kk++) {
            float4 a0 = *(float4*)&sA[kk][ty * 8];
            float4 a1 = *(float4*)&sA[kk][ty * 8 + 4];
            float4 b0 = *(float4*)&sB[kk][tx * 8];
            float4 b1 = *(float4*)&sB[kk][tx * 8 + 4];
            float a[8] = {a0.x, a0.y, a0.z, a0.w, a1.x, a1.y, a1.z, a1.w};
            float b[8] = {b0.x, b0.y, b0.z, b0.w, b1.x, b1.y, b1.z, b1.w};
            #pragma unroll
            for (int i = 0; i < 8; i++)
                #pragma unroll
                for (int j = 0; j < 8; j++)
                    acc[i][j] = fmaf(a[i], b[j], acc[i][j]);
        }
        __syncthreads();
    }

    #pragma unroll
    for (int i = 0; i < 8; i++) {
        int grow = by * 128 + ty * 8 + i;
        #pragma unroll
        for (int j4 = 0; j4 < 8; j4 += 4) {
            int gcol = bx * 128 + tx * 8 + j4;
            float4 v = make_float4(acc[i][j4], acc[i][j4 + 1],
                                   acc[i][j4 + 2], acc[i][j4 + 3]);
            if (MODE == 0) {
                int bb = grow >> 11;          // / SEQL
                int l  = grow & (SEQL - 1);
                int hh = gcol >> 6;           // / HDIM
                int d  = gcol & (HDIM - 1);
                *(float4*)(out + (((size_t)bb * NHEAD + hh) * SEQL + l) * HDIM + d) = v;
            } else {
                float4 rv = *(const float4*)(resid + (size_t)grow * DMODEL + gcol);
                v.x += rv.x; v.y += rv.y; v.z += rv.z; v.w += rv.w;
                *(float4*)(out + (size_t)grow * DMODEL + gcol) = v;
            }
        }
    }
}

// ---------------------------------------------------------------------------
// Banded flash attention: one block per (b, h, 64-query tile), 256 threads.
// 16x16 thread grid, each thread owns a 4x4 tile of S and O.
// Online softmax over up to 5 key tiles of 64 inside the window.
// ---------------------------------------------------------------------------
__global__ __launch_bounds__(256)
void attn_kernel()
{
    extern __shared__ float sm[];
    float (*sQt)[68] = (float(*)[68])(sm);                // sQt[d][q]
    float (*sKt)[68] = (float(*)[68])(sm + 64 * 68);      // sKt[d][k]
    float (*sV )[68] = (float(*)[68])(sm + 2 * 64 * 68);  // sV[k][d]
    float (*sPt)[68] = (float(*)[68])(sm + 3 * 64 * 68);  // sPt[k][q]

    const int tid = threadIdx.x;
    const int tx  = tid & 15;
    const int ty  = tid >> 4;
    const int qt  = blockIdx.x;
    const int h   = blockIdx.y;
    const int b   = blockIdx.z;

    const size_t base = ((size_t)b * NHEAD + h) * SEQL * HDIM;
    const float* Qg = g_Q + base;
    const float* Kg = g_K + base;
    const float* Vg = g_V + base;
    const int q0 = qt * 64;

    // Load Q tile transposed: 64 q-rows x 64 d, 1024 float4, 4 per thread
    #pragma unroll
    for (int r = 0; r < 4; r++) {
        int f   = tid + r * 256;
        int row = f >> 4;
        int c4  = (f & 15) << 2;
        float4 v = *(const float4*)(Qg + (size_t)(q0 + row) * HDIM + c4);
        sQt[c4 + 0][row] = v.x;
        sQt[c4 + 1][row] = v.y;
        sQt[c4 + 2][row] = v.z;
        sQt[c4 + 3][row] = v.w;
    }

    float m_run[4], l_run[4], o[4][4];
    #pragma unroll
    for (int i = 0; i < 4; i++) {
        m_run[i] = -1e30f;
        l_run[i] = 0.0f;
        #pragma unroll
        for (int j = 0; j < 4; j++) o[i][j] = 0.0f;
    }

    const int kt_lo = (qt >= 4) ? (qt - 4) : 0;
    for (int kt = kt_lo; kt <= qt; kt++) {
        __syncthreads();   // previous O-update done reading sPt/sV
        const int k0 = kt * 64;
        #pragma unroll
        for (int r = 0; r < 4; r++) {
            int f   = tid + r * 256;
            int row = f >> 4;
            int c4  = (f & 15) << 2;
            float4 kv = *(const float4*)(Kg + (size_t)(k0 + row) * HDIM + c4);
            sKt[c4 + 0][row] = kv.x;
            sKt[c4 + 1][row] = kv.y;
            sKt[c4 + 2][row] = kv.z;
            sKt[c4 + 3][row] = kv.w;
            *(float4*)&sV[row][c4] =
                *(const float4*)(Vg + (size_t)(k0 + row) * HDIM + c4);
        }
        __syncthreads();

        // S = Q K^T  (4x4 per thread)
        float s[4][4];
        #pragma unroll
        for (int i = 0; i < 4; i++)
            #pragma unroll
            for (int j = 0; j < 4; j++) s[i][j] = 0.0f;

        #pragma unroll 8
        for (int kk = 0; kk < 64; kk++) {
            float4 aq = *(float4*)&sQt[kk][ty * 4];
            float4 bk = *(float4*)&sKt[kk][tx * 4];
            float av[4] = {aq.x, aq.y, aq.z, aq.w};
            float bv[4] = {bk.x, bk.y, bk.z, bk.w};
            #pragma unroll
            for (int i = 0; i < 4; i++)
                #pragma unroll
                for (int j = 0; j < 4; j++)
                    s[i][j] = fmaf(av[i], bv[j], s[i][j]);
        }

        // scale + band mask
        #pragma unroll
        for (int i = 0; i < 4; i++) {
            int qi = q0 + ty * 4 + i;
            #pragma unroll
            for (int j = 0; j < 4; j++) {
                int kj = k0 + tx * 4 + j;
                bool valid = (kj <= qi) && (kj >= qi - (WINDOW - 1));
                s[i][j] = valid ? s[i][j] * 0.125f : -INFINITY;
            }
        }

        // online softmax (row groups of 16 lanes share a q-row)
        #pragma unroll
        for (int i = 0; i < 4; i++) {
            float mt = fmaxf(fmaxf(s[i][0], s[i][1]), fmaxf(s[i][2], s[i][3]));
            #pragma unroll
            for (int off = 8; off > 0; off >>= 1)
                mt = fmaxf(mt, __shfl_xor_sync(0xffffffffu, mt, off));
            float m_new = fmaxf(m_run[i], mt);
            float sc    = expf(m_run[i] - m_new);
            float ls    = 0.0f;
            #pragma unroll
            for (int j = 0; j < 4; j++) {
                float p = expf(s[i][j] - m_new);
                s[i][j] = p;
                ls += p;
            }
            #pragma unroll
            for (int off = 8; off > 0; off >>= 1)
                ls += __shfl_xor_sync(0xffffffffu, ls, off);
            l_run[i] = l_run[i] * sc + ls;
            m_run[i] = m_new;
            #pragma unroll
            for (int j = 0; j < 4; j++) o[i][j] *= sc;
        }

        // store P transposed: sPt[k][q]
        #pragma unroll
        for (int j = 0; j < 4; j++)
            #pragma unroll
            for (int i = 0; i < 4; i++)
                sPt[tx * 4 + j][ty * 4 + i] = s[i][j];
        __syncthreads();

        // O += P V
        #pragma unroll 8
        for (int kk = 0; kk < 64; kk++) {
            float4 ap = *(float4*)&sPt[kk][ty * 4];
            float4 vv = *(float4*)&sV[kk][tx * 4];
            float av[4] = {ap.x, ap.y, ap.z, ap.w};
            float bv[4] = {vv.x, vv.y, vv.z, vv.w};
            #pragma unroll
            for (int i = 0; i < 4; i++)
                #pragma unroll
                for (int j = 0; j < 4; j++)
                    o[i][j] = fmaf(av[i], bv[j], o[i][j]);
        }
    }

    // write context [B*L, H*dv]
    #pragma unroll
    for (int i = 0; i < 4; i++) {
        float il = 1.0f / l_run[i];
        int q = q0 + ty * 4 + i;
        float4 v = make_float4(o[i][0] * il, o[i][1] * il,
                               o[i][2] * il, o[i][3] * il);
        *(float4*)(g_ctx + ((size_t)b * SEQL + q) * DMODEL + h * HDIM + tx * 4) = v;
    }
}

// ---------------------------------------------------------------------------
// LayerNorm over last dim (512), one block per row, 256 threads x 2 elems.
// ---------------------------------------------------------------------------
__global__ __launch_bounds__(256)
void ln_kernel(const float* __restrict__ pre, float* __restrict__ out)
{
    __shared__ float red[16];
    const int row = blockIdx.x;
    const int tid = threadIdx.x;
    const float* x = pre + (size_t)row * DMODEL;

    float v0 = x[tid];
    float v1 = x[tid + 256];
    float s  = v0 + v1;
    float sq = v0 * v0 + v1 * v1;

    #pragma unroll
    for (int off = 16; off > 0; off >>= 1) {
        s  += __shfl_xor_sync(0xffffffffu, s, off);
        sq += __shfl_xor_sync(0xffffffffu, sq, off);
    }
    if ((tid & 31) == 0) {
        red[tid >> 5]     = s;
        red[8 + (tid >> 5)] = sq;
    }
    __syncthreads();
    float st = 0.0f, sqt = 0.0f;
    #pragma unroll
    for (int w = 0; w < 8; w++) { st += red[w]; sqt += red[8 + w]; }

    float mean = st * (1.0f / DMODEL);
    float var  = sqt * (1.0f / DMODEL) - mean * mean;
    float rstd = rsqrtf(var + 1e-5f);

    out[(size_t)row * DMODEL + tid]       = (v0 - mean) * rstd;
    out[(size_t)row * DMODEL + tid + 256] = (v1 - mean) * rstd;
}

// ---------------------------------------------------------------------------
extern "C" void kernel_launch(void* const* d_in, const int* in_sizes, int n_in,
                              void* d_out, int out_size)
{
    const float* iQ = (const float*)d_in[0];
    const float* iK = (const float*)d_in[1];
    const float* iV = (const float*)d_in[2];
    const float* wQ = (const float*)d_in[3];
    const float* wK = (const float*)d_in[4];
    const float* wV = (const float*)d_in[5];
    const float* wF = (const float*)d_in[6];
    float* out = (float*)d_out;

    float *pQ, *pK, *pV, *pCtx, *pPre;
    cudaGetSymbolAddress((void**)&pQ,   g_Q);
    cudaGetSymbolAddress((void**)&pK,   g_K);
    cudaGetSymbolAddress((void**)&pV,   g_V);
    cudaGetSymbolAddress((void**)&pCtx, g_ctx);
    cudaGetSymbolAddress((void**)&pPre, g_pre);

    dim3 tg(256);
    dim3 gg(DMODEL / 128, MTOT / 128);   // (4, 64)

    gemm512_kernel<0><<<gg, tg>>>(iQ, wQ, nullptr, pQ);
    gemm512_kernel<0><<<gg, tg>>>(iK, wK, nullptr, pK);
    gemm512_kernel<0><<<gg, tg>>>(iV, wV, nullptr, pV);

    int smem = 4 * 64 * 68 * (int)sizeof(float);   // 69632 B
    cudaFuncSetAttribute((const void*)attn_kernel,
                         cudaFuncAttributeMaxDynamicSharedMemorySize, smem);
    dim3 ga(SEQL / 64, NHEAD, NB);
    attn_kernel<<<ga, tg, smem>>>();

    gemm512_kernel<1><<<gg, tg>>>(pCtx, wF, iQ, pPre);

    ln_kernel<<<MTOT, tg>>>(pPre, out);
}

// round 3
// speedup vs baseline: 1.7489x; 1.7489x over previous
#include <cuda_runtime.h>
#include <cuda_bf16.h>
#include <math.h>
#include <stdint.h>

#define NB 4
#define SEQL 2048
#define DMODEL 512
#define NHEAD 8
#define HDIM 64
#define WINDOW 256
#define MTOT (NB*SEQL)   // 8192

// Scratch (device globals; no allocation allowed)
__device__ __align__(16) float g_Q[MTOT*DMODEL];     // [B,L,H*d] fp32
__device__ __align__(16) float g_K[MTOT*DMODEL];
__device__ __align__(16) float g_V[MTOT*DMODEL];
__device__ __align__(16) float g_pre[MTOT*DMODEL];   // pre-LayerNorm
__device__ __align__(16) __nv_bfloat16 g_Wh[4*DMODEL*DMODEL];  // W^T hi, [w][n][k]
__device__ __align__(16) __nv_bfloat16 g_Wl[4*DMODEL*DMODEL];  // W^T lo
__device__ __align__(16) __nv_bfloat16 g_Xh[3*MTOT*DMODEL];    // inputs hi
__device__ __align__(16) __nv_bfloat16 g_Xl[3*MTOT*DMODEL];    // inputs lo
__device__ __align__(16) __nv_bfloat16 g_Ch[MTOT*DMODEL];      // ctx hi
__device__ __align__(16) __nv_bfloat16 g_Cl[MTOT*DMODEL];      // ctx lo

// ---------------------------------------------------------------------------
// Generic-PTX helpers (NO tcgen05 — harness compiles for compute_103)
// ---------------------------------------------------------------------------
__device__ __forceinline__ uint32_t smem_u32(const void* p) {
    uint32_t a;
    asm("{ .reg .u64 t; cvta.to.shared.u64 t, %1; cvt.u32.u64 %0, t; }"
        : "=r"(a) : "l"(p));
    return a;
}

__device__ __forceinline__ void cpa16(uint32_t dst, const void* src) {
    asm volatile("cp.async.cg.shared.global [%0], [%1], 16;"
                 :: "r"(dst), "l"(src));
}
#define CP_COMMIT() asm volatile("cp.async.commit_group;")
#define CP_WAIT(n)  asm volatile("cp.async.wait_group " #n ";")

__device__ __forceinline__ void ldmx4(uint32_t addr, uint32_t* r) {
    asm volatile("ldmatrix.sync.aligned.m8n8.x4.shared.b16 {%0,%1,%2,%3}, [%4];"
                 : "=r"(r[0]), "=r"(r[1]), "=r"(r[2]), "=r"(r[3]) : "r"(addr));
}

__device__ __forceinline__ void mma16816(float* d, const uint32_t* a, const uint32_t* b) {
    asm volatile("mma.sync.aligned.m16n8k16.row.col.f32.bf16.bf16.f32 "
                 "{%0,%1,%2,%3}, {%4,%5,%6,%7}, {%8,%9}, {%0,%1,%2,%3};"
                 : "+f"(d[0]), "+f"(d[1]), "+f"(d[2]), "+f"(d[3])
                 : "r"(a[0]), "r"(a[1]), "r"(a[2]), "r"(a[3]),
                   "r"(b[0]), "r"(b[1]));
}

// ---------------------------------------------------------------------------
// Prep: transpose + bf16-split weights: W[k][n] -> Wt_hi/lo[n][k]
// ---------------------------------------------------------------------------
__global__ __launch_bounds__(256)
void prep_w_kernel(const float* __restrict__ w0, const float* __restrict__ w1,
                   const float* __restrict__ w2, const float* __restrict__ w3)
{
    __shared__ float s[32][33];
    const int wsel = blockIdx.z;
    const float* W = (wsel == 0) ? w0 : (wsel == 1) ? w1 : (wsel == 2) ? w2 : w3;
    const int k0 = blockIdx.x * 32, n0 = blockIdx.y * 32;
    const int tx = threadIdx.x, ty = threadIdx.y;

    #pragma unroll
    for (int i = 0; i < 4; i++)
        s[ty + 8 * i][tx] = W[(size_t)(k0 + ty + 8 * i) * DMODEL + n0 + tx];
    __syncthreads();

    const size_t base = (size_t)wsel * DMODEL * DMODEL;
    #pragma unroll
    for (int i = 0; i < 4; i++) {
        int n = n0 + ty + 8 * i, k = k0 + tx;
        float x = s[tx][ty + 8 * i];
        __nv_bfloat16 h = __float2bfloat16(x);
        float lo = x - __bfloat162float(h);
        g_Wh[base + (size_t)n * DMODEL + k] = h;
        g_Wl[base + (size_t)n * DMODEL + k] = __float2bfloat16(lo);
    }
}

// ---------------------------------------------------------------------------
// Prep: split inputs fp32 -> bf16 hi/lo (3 matrices, [8192,512])
// ---------------------------------------------------------------------------
__global__ __launch_bounds__(256)
void prep_x_kernel(const float* __restrict__ x0, const float* __restrict__ x1,
                   const float* __restrict__ x2)
{
    const int sel = blockIdx.y;
    const float* x = (sel == 0) ? x0 : (sel == 1) ? x1 : x2;
    size_t i4 = ((size_t)blockIdx.x * 256 + threadIdx.x);
    float4 v = ((const float4*)x)[i4];
    __nv_bfloat16 h0 = __float2bfloat16(v.x), h1 = __float2bfloat16(v.y);
    __nv_bfloat16 h2 = __float2bfloat16(v.z), h3 = __float2bfloat16(v.w);
    __nv_bfloat16 l0 = __float2bfloat16(v.x - __bfloat162float(h0));
    __nv_bfloat16 l1 = __float2bfloat16(v.y - __bfloat162float(h1));
    __nv_bfloat16 l2 = __float2bfloat16(v.z - __bfloat162float(h2));
    __nv_bfloat16 l3 = __float2bfloat16(v.w - __bfloat162float(h3));
    uint2 uh, ul;
    uh.x = ((uint32_t)__bfloat16_as_ushort(h1) << 16) | __bfloat16_as_ushort(h0);
    uh.y = ((uint32_t)__bfloat16_as_ushort(h3) << 16) | __bfloat16_as_ushort(h2);
    ul.x = ((uint32_t)__bfloat16_as_ushort(l1) << 16) | __bfloat16_as_ushort(l0);
    ul.y = ((uint32_t)__bfloat16_as_ushort(l3) << 16) | __bfloat16_as_ushort(l2);
    const size_t base = (size_t)sel * MTOT * DMODEL;
    ((uint2*)(g_Xh + base))[i4] = uh;
    ((uint2*)(g_Xl + base))[i4] = ul;
}

// ---------------------------------------------------------------------------
// Tensor-core GEMM via mma.sync (bf16, 3-term split, fp32 accum):
// C[8192,512] = A @ W.  Block 128x128, BK=64, 8 warps, warp tile 64x32,
// cp.async double-buffered, XOR-swizzled smem + ldmatrix.
// MODE 0: store C; MODE 1: store C + resid.
// ---------------------------------------------------------------------------
#define STG_BYTES 65536
#define AH_OFF 0
#define AL_OFF 16384
#define BH_OFF 32768
#define BL_OFF 49152

__device__ __forceinline__ void stage_load(uint32_t sbase,
                                           const __nv_bfloat16* __restrict__ g,
                                           int row0, int k0, int tid)
{
    #pragma unroll
    for (int i = 0; i < 4; i++) {
        int idx = tid + i * 256;
        int r = idx >> 3, c = idx & 7;
        const void* src = g + (size_t)(row0 + r) * DMODEL + k0 + c * 8;
        uint32_t dst = sbase + (uint32_t)r * 128 + (uint32_t)((c ^ (r & 7)) << 4);
        cpa16(dst, src);
    }
}

template<int MODE>
__global__ __launch_bounds__(256)
void gemm_tc(const __nv_bfloat16* __restrict__ Ah, const __nv_bfloat16* __restrict__ Al,
             const __nv_bfloat16* __restrict__ Bh, const __nv_bfloat16* __restrict__ Bl,
             const float* __restrict__ resid, float* __restrict__ out)
{
    extern __shared__ char dyn[];
    const uint32_t sb = smem_u32(dyn);
    const int tid  = threadIdx.x;
    const int wid  = tid >> 5, lane = tid & 31;
    const int wm   = wid & 1, wn = wid >> 1;          // 2 x 4 warp grid
    const int bx   = blockIdx.x, by = blockIdx.y;
    const int arow = by * 128, brow = bx * 128;

    float d[4][4][4];
    #pragma unroll
    for (int mi = 0; mi < 4; mi++)
        #pragma unroll
        for (int ni = 0; ni < 4; ni++)
            #pragma unroll
            for (int q = 0; q < 4; q++) d[mi][ni][q] = 0.0f;

    // prologue: stage 0
    stage_load(sb + AH_OFF, Ah, arow, 0, tid);
    stage_load(sb + AL_OFF, Al, arow, 0, tid);
    stage_load(sb + BH_OFF, Bh, brow, 0, tid);
    stage_load(sb + BL_OFF, Bl, brow, 0, tid);
    CP_COMMIT();

    const int g8 = lane >> 3, r8 = lane & 7;

    for (int c = 0; c < 8; c++) {
        if (c < 7) {
            uint32_t s2 = sb + (uint32_t)((c + 1) & 1) * STG_BYTES;
            int k0 = (c + 1) * 64;
            stage_load(s2 + AH_OFF, Ah, arow, k0, tid);
            stage_load(s2 + AL_OFF, Al, arow, k0, tid);
            stage_load(s2 + BH_OFF, Bh, brow, k0, tid);
            stage_load(s2 + BL_OFF, Bl, brow, k0, tid);
            CP_COMMIT();
            CP_WAIT(1);
        } else {
            CP_WAIT(0);
        }
        __syncthreads();

        const uint32_t ss = sb + (uint32_t)(c & 1) * STG_BYTES;
        #pragma unroll
        for (int k16 = 0; k16 < 4; k16++) {
            uint32_t ah[4][4], al[4][4], bh[8], bl[8];
            // A frags: 4 m16 tiles; lane addr: row=m0+r8+(g8&1)*8, chunk=k16*2+(g8>>1)
            #pragma unroll
            for (int mi = 0; mi < 4; mi++) {
                int row = wm * 64 + mi * 16 + r8 + (g8 & 1) * 8;
                int ch  = k16 * 2 + (g8 >> 1);
                uint32_t off = (uint32_t)row * 128 + (uint32_t)((ch ^ (row & 7)) << 4);
                ldmx4(ss + AH_OFF + off, ah[mi]);
                ldmx4(ss + AL_OFF + off, al[mi]);
            }
            // B frags: 2x (pair of n8 tiles); row=n0+r8+(g8>>1)*8, chunk=k16*2+(g8&1)
            #pragma unroll
            for (int np = 0; np < 2; np++) {
                int row = wn * 32 + np * 16 + r8 + (g8 >> 1) * 8;
                int ch  = k16 * 2 + (g8 & 1);
                uint32_t off = (uint32_t)row * 128 + (uint32_t)((ch ^ (row & 7)) << 4);
                ldmx4(ss + BH_OFF + off, &bh[np * 4]);
                ldmx4(ss + BL_OFF + off, &bl[np * 4]);
            }
            #pragma unroll
            for (int mi = 0; mi < 4; mi++)
                #pragma unroll
                for (int ni = 0; ni < 4; ni++) {
                    mma16816(d[mi][ni], ah[mi], &bh[ni * 2]);
                    mma16816(d[mi][ni], al[mi], &bh[ni * 2]);
                    mma16816(d[mi][ni], ah[mi], &bl[ni * 2]);
                }
        }
        __syncthreads();
    }

    // epilogue: d0,d1 -> (row, col..col+1); d2,d3 -> (row+8, ...)
    const int rbase = by * 128 + wm * 64 + (lane >> 2);
    const int cbase = bx * 128 + wn * 32 + (lane & 3) * 2;
    #pragma unroll
    for (int mi = 0; mi < 4; mi++) {
        #pragma unroll
        for (int ni = 0; ni < 4; ni++) {
            int col = cbase + ni * 8;
            #pragma unroll
            for (int half = 0; half < 2; half++) {
                int row = rbase + mi * 16 + half * 8;
                float2 v = make_float2(d[mi][ni][half * 2], d[mi][ni][half * 2 + 1]);
                if (MODE == 1) {
                    float2 rv = *(const float2*)(resid + (size_t)row * DMODEL + col);
                    v.x += rv.x; v.y += rv.y;
                }
                *(float2*)(out + (size_t)row * DMODEL + col) = v;
            }
        }
    }
}

// ---------------------------------------------------------------------------
// Banded flash attention (fp32, proven R1 math; [B,L,H*d] layout).
// Epilogue writes ctx as bf16 hi/lo directly.
// ---------------------------------------------------------------------------
__global__ __launch_bounds__(256)
void attn_kernel()
{
    extern __shared__ float sm[];
    float (*sQt)[68] = (float(*)[68])(sm);
    float (*sKt)[68] = (float(*)[68])(sm + 64 * 68);
    float (*sV )[68] = (float(*)[68])(sm + 2 * 64 * 68);
    float (*sPt)[68] = (float(*)[68])(sm + 3 * 64 * 68);

    const int tid = threadIdx.x;
    const int tx  = tid & 15;
    const int ty  = tid >> 4;
    const int qt  = blockIdx.x;
    const int hh  = blockIdx.y;
    const int b   = blockIdx.z;

    const size_t base = (size_t)b * SEQL * DMODEL + hh * HDIM;
    const float* Qg = g_Q + base;
    const float* Kg = g_K + base;
    const float* Vg = g_V + base;
    const int q0 = qt * 64;

    #pragma unroll
    for (int r = 0; r < 4; r++) {
        int f   = tid + r * 256;
        int row = f >> 4;
        int c4  = (f & 15) << 2;
        float4 v = *(const float4*)(Qg + (size_t)(q0 + row) * DMODEL + c4);
        sQt[c4 + 0][row] = v.x;
        sQt[c4 + 1][row] = v.y;
        sQt[c4 + 2][row] = v.z;
        sQt[c4 + 3][row] = v.w;
    }

    float m_run[4], l_run[4], o[4][4];
    #pragma unroll
    for (int i = 0; i < 4; i++) {
        m_run[i] = -1e30f;
        l_run[i] = 0.0f;
        #pragma unroll
        for (int j = 0; j < 4; j++) o[i][j] = 0.0f;
    }

    const int kt_lo = (qt >= 4) ? (qt - 4) : 0;
    for (int kt = kt_lo; kt <= qt; kt++) {
        __syncthreads();
        const int k0 = kt * 64;
        #pragma unroll
        for (int r = 0; r < 4; r++) {
            int f   = tid + r * 256;
            int row = f >> 4;
            int c4  = (f & 15) << 2;
            float4 kv = *(const float4*)(Kg + (size_t)(k0 + row) * DMODEL + c4);
            sKt[c4 + 0][row] = kv.x;
            sKt[c4 + 1][row] = kv.y;
            sKt[c4 + 2][row] = kv.z;
            sKt[c4 + 3][row] = kv.w;
            *(float4*)&sV[row][c4] =
                *(const float4*)(Vg + (size_t)(k0 + row) * DMODEL + c4);
        }
        __syncthreads();

        float s[4][4];
        #pragma unroll
        for (int i = 0; i < 4; i++)
            #pragma unroll
            for (int j = 0; j < 4; j++) s[i][j] = 0.0f;

        #pragma unroll 8
        for (int kk = 0; kk < 64; kk++) {
            float4 aq = *(float4*)&sQt[kk][ty * 4];
            float4 bk = *(float4*)&sKt[kk][tx * 4];
            float av[4] = {aq.x, aq.y, aq.z, aq.w};
            float bv[4] = {bk.x, bk.y, bk.z, bk.w};
            #pragma unroll
            for (int i = 0; i < 4; i++)
                #pragma unroll
                for (int j = 0; j < 4; j++)
                    s[i][j] = fmaf(av[i], bv[j], s[i][j]);
        }

        #pragma unroll
        for (int i = 0; i < 4; i++) {
            int qi = q0 + ty * 4 + i;
            #pragma unroll
            for (int j = 0; j < 4; j++) {
                int kj = k0 + tx * 4 + j;
                bool valid = (kj <= qi) && (kj >= qi - (WINDOW - 1));
                s[i][j] = valid ? s[i][j] * 0.125f : -INFINITY;
            }
        }

        #pragma unroll
        for (int i = 0; i < 4; i++) {
            float mt = fmaxf(fmaxf(s[i][0], s[i][1]), fmaxf(s[i][2], s[i][3]));
            #pragma unroll
            for (int off = 8; off > 0; off >>= 1)
                mt = fmaxf(mt, __shfl_xor_sync(0xffffffffu, mt, off));
            float m_new = fmaxf(m_run[i], mt);
            float sc    = expf(m_run[i] - m_new);
            float ls    = 0.0f;
            #pragma unroll
            for (int j = 0; j < 4; j++) {
                float p = expf(s[i][j] - m_new);
                s[i][j] = p;
                ls += p;
            }
            #pragma unroll
            for (int off = 8; off > 0; off >>= 1)
                ls += __shfl_xor_sync(0xffffffffu, ls, off);
            l_run[i] = l_run[i] * sc + ls;
            m_run[i] = m_new;
            #pragma unroll
            for (int j = 0; j < 4; j++) o[i][j] *= sc;
        }

        #pragma unroll
        for (int j = 0; j < 4; j++)
            #pragma unroll
            for (int i = 0; i < 4; i++)
                sPt[tx * 4 + j][ty * 4 + i] = s[i][j];
        __syncthreads();

        #pragma unroll 8
        for (int kk = 0; kk < 64; kk++) {
            float4 ap = *(float4*)&sPt[kk][ty * 4];
            float4 vv = *(float4*)&sV[kk][tx * 4];
            float av[4] = {ap.x, ap.y, ap.z, ap.w};
            float bv[4] = {vv.x, vv.y, vv.z, vv.w};
            #pragma unroll
            for (int i = 0; i < 4; i++)
                #pragma unroll
                for (int j = 0; j < 4; j++)
                    o[i][j] = fmaf(av[i], bv[j], o[i][j]);
        }
    }

    // write context [B*L, H*dv] as bf16 hi/lo (ready for out-proj GEMM)
    #pragma unroll
    for (int i = 0; i < 4; i++) {
        float il = 1.0f / l_run[i];
        int q = q0 + ty * 4 + i;
        float vv[4] = {o[i][0] * il, o[i][1] * il, o[i][2] * il, o[i][3] * il};
        __nv_bfloat16 h0 = __float2bfloat16(vv[0]), h1 = __float2bfloat16(vv[1]);
        __nv_bfloat16 h2 = __float2bfloat16(vv[2]), h3 = __float2bfloat16(vv[3]);
        __nv_bfloat16 l0 = __float2bfloat16(vv[0] - __bfloat162float(h0));
        __nv_bfloat16 l1 = __float2bfloat16(vv[1] - __bfloat162float(h1));
        __nv_bfloat16 l2 = __float2bfloat16(vv[2] - __bfloat162float(h2));
        __nv_bfloat16 l3 = __float2bfloat16(vv[3] - __bfloat162float(h3));
        uint2 uh, ul;
        uh.x = ((uint32_t)__bfloat16_as_ushort(h1) << 16) | __bfloat16_as_ushort(h0);
        uh.y = ((uint32_t)__bfloat16_as_ushort(h3) << 16) | __bfloat16_as_ushort(h2);
        ul.x = ((uint32_t)__bfloat16_as_ushort(l1) << 16) | __bfloat16_as_ushort(l0);
        ul.y = ((uint32_t)__bfloat16_as_ushort(l3) << 16) | __bfloat16_as_ushort(l2);
        size_t off = ((size_t)b * SEQL + q) * DMODEL + hh * HDIM + tx * 4;
        *(uint2*)(g_Ch + off) = uh;
        *(uint2*)(g_Cl + off) = ul;
    }
}

// ---------------------------------------------------------------------------
// LayerNorm over last dim (512), one block per row.
// ---------------------------------------------------------------------------
__global__ __launch_bounds__(256)
void ln_kernel(const float* __restrict__ pre, float* __restrict__ out)
{
    __shared__ float red[16];
    const int row = blockIdx.x;
    const int tid = threadIdx.x;
    const float* x = pre + (size_t)row * DMODEL;

    float v0 = x[tid];
    float v1 = x[tid + 256];
    float s  = v0 + v1;
    float sq = v0 * v0 + v1 * v1;

    #pragma unroll
    for (int off = 16; off > 0; off >>= 1) {
        s  += __shfl_xor_sync(0xffffffffu, s, off);
        sq += __shfl_xor_sync(0xffffffffu, sq, off);
    }
    if ((tid & 31) == 0) {
        red[tid >> 5]       = s;
        red[8 + (tid >> 5)] = sq;
    }
    __syncthreads();
    float st = 0.0f, sqt = 0.0f;
    #pragma unroll
    for (int w = 0; w < 8; w++) { st += red[w]; sqt += red[8 + w]; }

    float mean = st * (1.0f / DMODEL);
    float var  = sqt * (1.0f / DMODEL) - mean * mean;
    float rstd = rsqrtf(var + 1e-5f);

    out[(size_t)row * DMODEL + tid]       = (v0 - mean) * rstd;
    out[(size_t)row * DMODEL + tid + 256] = (v1 - mean) * rstd;
}

// ---------------------------------------------------------------------------
extern "C" void kernel_launch(void* const* d_in, const int* in_sizes, int n_in,
                              void* d_out, int out_size)
{
    const float* iQ = (const float*)d_in[0];
    const float* iK = (const float*)d_in[1];
    const float* iV = (const float*)d_in[2];
    const float* wQ = (const float*)d_in[3];
    const float* wK = (const float*)d_in[4];
    const float* wV = (const float*)d_in[5];
    const float* wF = (const float*)d_in[6];
    float* out = (float*)d_out;

    float *pQ, *pK, *pV, *pPre;
    __nv_bfloat16 *pWh, *pWl, *pXh, *pXl, *pCh, *pCl;
    cudaGetSymbolAddress((void**)&pQ,   g_Q);
    cudaGetSymbolAddress((void**)&pK,   g_K);
    cudaGetSymbolAddress((void**)&pV,   g_V);
    cudaGetSymbolAddress((void**)&pPre, g_pre);
    cudaGetSymbolAddress((void**)&pWh,  g_Wh);
    cudaGetSymbolAddress((void**)&pWl,  g_Wl);
    cudaGetSymbolAddress((void**)&pXh,  g_Xh);
    cudaGetSymbolAddress((void**)&pXl,  g_Xl);
    cudaGetSymbolAddress((void**)&pCh,  g_Ch);
    cudaGetSymbolAddress((void**)&pCl,  g_Cl);

    // Prep
    prep_w_kernel<<<dim3(16, 16, 4), dim3(32, 8)>>>(wQ, wK, wV, wF);
    prep_x_kernel<<<dim3(MTOT * DMODEL / 4 / 256, 3), 256>>>(iQ, iK, iV);

    // Tensor-core GEMMs
    const int gemm_smem = 2 * STG_BYTES;   // 131072
    cudaFuncSetAttribute((const void*)gemm_tc<0>,
                         cudaFuncAttributeMaxDynamicSharedMemorySize, gemm_smem);
    cudaFuncSetAttribute((const void*)gemm_tc<1>,
                         cudaFuncAttributeMaxDynamicSharedMemorySize, gemm_smem);

    const size_t WSZ = (size_t)DMODEL * DMODEL;
    const size_t XSZ = (size_t)MTOT * DMODEL;
    dim3 gg(DMODEL / 128, MTOT / 128);   // (4, 64)
    gemm_tc<0><<<gg, 256, gemm_smem>>>(pXh + 0 * XSZ, pXl + 0 * XSZ,
                                       pWh + 0 * WSZ, pWl + 0 * WSZ, nullptr, pQ);
    gemm_tc<0><<<gg, 256, gemm_smem>>>(pXh + 1 * XSZ, pXl + 1 * XSZ,
                                       pWh + 1 * WSZ, pWl + 1 * WSZ, nullptr, pK);
    gemm_tc<0><<<gg, 256, gemm_smem>>>(pXh + 2 * XSZ, pXl + 2 * XSZ,
                                       pWh + 2 * WSZ, pWl + 2 * WSZ, nullptr, pV);

    // Attention
    int attn_smem = 4 * 64 * 68 * (int)sizeof(float);
    cudaFuncSetAttribute((const void*)attn_kernel,
                         cudaFuncAttributeMaxDynamicSharedMemorySize, attn_smem);
    dim3 ga(SEQL / 64, NHEAD, NB);
    attn_kernel<<<ga, 256, attn_smem>>>();

    // Output projection + residual
    gemm_tc<1><<<gg, 256, gemm_smem>>>(pCh, pCl,
                                       pWh + 3 * WSZ, pWl + 3 * WSZ, iQ, pPre);

    ln_kernel<<<MTOT, 256>>>(pPre, out);
}